// round 5
// baseline (speedup 1.0000x reference)
#include <cuda_runtime.h>
#include <stdint.h>

// ChannelPair2D: out[p, k] = x[p, i_k] * x[p, j_k], (i,j) i<j row-major triu.
// C=64 -> 2016 pairs, 65536 pixels. HBM-write-bound (~504 MiB out).
//
// R5: compile-time quad-descriptor table SORTED fast-first -> warp-uniform
// branches (no divergence), no per-block table math. PPB=16. Fast-path body:
// LDS + LDS.128 + 4*FMUL + STG.128 per quad-pixel.

#define C_CH  64
#define NPAIR 2016
#define NQ    504               // NPAIR/4 quads
#define TPB   256
#define PPB   16                // pixels per block
#define PLANE (PPB * C_CH)      // floats per replica plane (1024)

// ---------------- compile-time quad table ----------------
struct Q4s  { unsigned x, y, z, w; };
struct QTab { Q4s v[2 * TPB]; };

constexpr int off_of(int i) { return i * (127 - i) / 2; }

constexpr QTab build_qtab() {
    QTab t{};
    for (int s = 0; s < 2 * TPB; ++s) {
        t.v[s].x = 0u; t.v[s].y = 0xFFFFFFFFu; t.v[s].z = 0u; t.v[s].w = 0u;
    }
    int nfast = 0;
    for (int q = 0; q < NQ; ++q) {
        int k = 4 * q, i = 0;
        while (off_of(i + 1) <= k) ++i;
        int j = i + 1 + (k - off_of(i));
        if (j + 3 <= 63) ++nfast;
    }
    int pf = 0, pb = nfast;
    for (int q = 0; q < NQ; ++q) {
        int k = 4 * q, i = 0;
        while (off_of(i + 1) <= k) ++i;
        int j = i + 1 + (k - off_of(i));
        if (j + 3 <= 63) {
            // fast: bit31 flag | xi byte-offset [0:8) | shifted-vec byte-offset [8:22)
            t.v[pf].x = 0x80000000u
                      | (unsigned)(i * 4)
                      | ((unsigned)(((j & 3) * PLANE + (j & ~3)) * 4) << 8);
            t.v[pf].y = (unsigned)q;
            ++pf;
        } else {
            // boundary: 8 byte-offsets (idx*4 <= 252) packed into z,w
            unsigned b[8] = {0,0,0,0,0,0,0,0};
            int ii = i, jj = j;
            for (int e = 0; e < 4; ++e) {
                b[2*e]   = (unsigned)(ii * 4);
                b[2*e+1] = (unsigned)(jj * 4);
                ++jj; if (jj > 63) { ++ii; jj = ii + 1; }
            }
            t.v[pb].x = 0u;
            t.v[pb].y = (unsigned)q;
            t.v[pb].z = b[0] | (b[1] << 8) | (b[2] << 16) | (b[3] << 24);
            t.v[pb].w = b[4] | (b[5] << 8) | (b[6] << 16) | (b[7] << 24);
            ++pb;
        }
    }
    return t;
}

__device__ const QTab g_qtab = build_qtab();

// ---------------- per-role inner loops ----------------
__device__ __forceinline__ void do_fast(const char* __restrict__ bf, unsigned meta,
                                        float4* __restrict__ o, int pc) {
    const char* xiP = bf + (meta & 0xFFu);
    const char* svP = bf + ((meta >> 8) & 0x3FFFu);
    #pragma unroll 4
    for (int p = 0; p < pc; ++p) {
        const float  xi = *(const float*)(xiP + p * 256);
        const float4 v  = *(const float4*)(svP + p * 256);
        float4 r;
        r.x = xi * v.x; r.y = xi * v.y; r.z = xi * v.z; r.w = xi * v.w;
        o[(size_t)p * NQ] = r;
    }
}

__device__ __forceinline__ void do_bnd(const char* __restrict__ bf, unsigned z, unsigned w,
                                       float4* __restrict__ o, int pc) {
    const unsigned i0 = z & 255u, j0 = (z >> 8) & 255u, i1 = (z >> 16) & 255u, j1 = z >> 24;
    const unsigned i2 = w & 255u, j2 = (w >> 8) & 255u, i3 = (w >> 16) & 255u, j3 = w >> 24;
    #pragma unroll 4
    for (int p = 0; p < pc; ++p) {
        const char* b = bf + p * 256;
        float4 r;
        r.x = *(const float*)(b + i0) * *(const float*)(b + j0);
        r.y = *(const float*)(b + i1) * *(const float*)(b + j1);
        r.z = *(const float*)(b + i2) * *(const float*)(b + j2);
        r.w = *(const float*)(b + i3) * *(const float*)(b + j3);
        o[(size_t)p * NQ] = r;
    }
}

// ---------------- kernel ----------------
__global__ __launch_bounds__(TPB)
void channelpair_kernel(const float* __restrict__ x,
                        float* __restrict__ out,
                        int npix) {
    // Shifted replicas: plane s holds x_p[c+s]; fast path reads x[j..j+3] as
    // one aligned LDS.128 at plane j&3, col j&~3.
    __shared__ __align__(16) float Bf[4 * PLANE];   // 16 KB

    const int tid  = threadIdx.x;
    const int pix0 = blockIdx.x * PPB;

    // Descriptors (sorted fast-first), coalesced LDG.128
    const uint4* qt = (const uint4*)g_qtab.v;
    const uint4 d0 = qt[tid];
    const uint4 d1 = qt[tid + TPB];

    // Plane 0: PPB*64 floats = 256 float4 = exactly TPB loads
    {
        const float4* src = (const float4*)(x + (size_t)pix0 * C_CH);
        const int pix = pix0 + tid / (C_CH / 4);
        ((float4*)Bf)[tid] = (pix < npix) ? src[tid] : make_float4(0.f, 0.f, 0.f, 0.f);
    }
    __syncthreads();

    // Replica planes 1..3 (conflict-free scalar copies)
    for (int t = tid; t < 3 * PLANE; t += TPB) {
        const int s = 1 + t / PLANE;
        const int r = t % PLANE;
        const int c = r & 63;
        int sc = c + s; if (sc > 63) sc = 63;
        Bf[s * PLANE + r] = Bf[(r - c) + sc];
    }
    __syncthreads();

    const int rem = npix - pix0;
    const int pc  = rem >= PPB ? PPB : rem;

    float4* out4 = (float4*)out + (size_t)pix0 * NQ;
    const char* bf = (const char*)Bf;

    // w0: sorted slots 0..255 are all fast (nfast >= 442); branch is uniform
    if (d0.x >> 31)        do_fast(bf, d0.x, out4 + d0.y, pc);
    else if (d0.y < NQ)    do_bnd(bf, d0.z, d0.w, out4 + d0.y, pc);

    // w1: slots 256..511 — fast block, then boundary block, then inactive
    if (d1.x >> 31)        do_fast(bf, d1.x, out4 + d1.y, pc);
    else if (d1.y < NQ)    do_bnd(bf, d1.z, d1.w, out4 + d1.y, pc);
}

extern "C" void kernel_launch(void* const* d_in, const int* in_sizes, int n_in,
                              void* d_out, int out_size) {
    const float* x = (const float*)d_in[0];
    float* out = (float*)d_out;

    const int npix = in_sizes[0] / C_CH;            // 65536
    const int nblk = (npix + PPB - 1) / PPB;        // 4096

    channelpair_kernel<<<nblk, TPB>>>(x, out, npix);
}

// round 6
// speedup vs baseline: 1.3894x; 1.3894x over previous
#include <cuda_runtime.h>
#include <stdint.h>

// ChannelPair2D: out[p, k] = x[p, i_k] * x[p, j_k], (i,j) i<j row-major triu.
// C=64 -> 2016 pairs, 65536 pixels. HBM-write-bound (~504 MiB out).
//
// R6 = R2's proven execution geometry (outer unroll-1 pixel loop, block-wide
// contiguous stores per pixel, high occupancy) + R5's compile-time sorted
// descriptor table (no per-block table math, no per-iter table LDS,
// warp-uniform branches).

#define C_CH  64
#define NPAIR 2016
#define NQ    504               // NPAIR/4 quads
#define TPB   256
#define PPB   8                 // pixels per block
#define PLANE (PPB * C_CH)      // floats per replica plane (512)

// ---------------- compile-time quad table (sorted fast-first) ----------------
struct Q4s  { unsigned x, y, z, w; };
struct QTab { Q4s v[2 * TPB]; };

constexpr int off_of(int i) { return i * (127 - i) / 2; }

constexpr QTab build_qtab() {
    QTab t{};
    for (int s = 0; s < 2 * TPB; ++s) {
        t.v[s].x = 0u; t.v[s].y = 0xFFFFFFFFu; t.v[s].z = 0u; t.v[s].w = 0u;
    }
    int nfast = 0;
    for (int q = 0; q < NQ; ++q) {
        int k = 4 * q, i = 0;
        while (off_of(i + 1) <= k) ++i;
        int j = i + 1 + (k - off_of(i));
        if (j + 3 <= 63) ++nfast;
    }
    int pf = 0, pb = nfast;
    for (int q = 0; q < NQ; ++q) {
        int k = 4 * q, i = 0;
        while (off_of(i + 1) <= k) ++i;
        int j = i + 1 + (k - off_of(i));
        if (j + 3 <= 63) {
            // fast: bit31 | xi byte-off [0:8) | shifted-vec byte-off [8:22)
            t.v[pf].x = 0x80000000u
                      | (unsigned)(i * 4)
                      | ((unsigned)(((j & 3) * PLANE + (j & ~3)) * 4) << 8);
            t.v[pf].y = (unsigned)q;
            ++pf;
        } else {
            // boundary: 8 byte-offsets packed into z,w
            unsigned b[8] = {0,0,0,0,0,0,0,0};
            int ii = i, jj = j;
            for (int e = 0; e < 4; ++e) {
                b[2*e]   = (unsigned)(ii * 4);
                b[2*e+1] = (unsigned)(jj * 4);
                ++jj; if (jj > 63) { ++ii; jj = ii + 1; }
            }
            t.v[pb].x = 0u;
            t.v[pb].y = (unsigned)q;
            t.v[pb].z = b[0] | (b[1] << 8) | (b[2] << 16) | (b[3] << 24);
            t.v[pb].w = b[4] | (b[5] << 8) | (b[6] << 16) | (b[7] << 24);
            ++pb;
        }
    }
    return t;
}

__device__ const QTab g_qtab = build_qtab();

// ---------------- kernel ----------------
__global__ __launch_bounds__(TPB)
void channelpair_kernel(const float* __restrict__ x,
                        float* __restrict__ out,
                        int npix) {
    // Shifted replicas: plane s holds x_p[c+s]; fast path reads x[j..j+3] as
    // one aligned LDS.128 at plane j&3, col j&~3.
    __shared__ __align__(16) float Bf[4 * PLANE];   // 8 KB

    const int tid  = threadIdx.x;
    const int pix0 = blockIdx.x * PPB;

    // Descriptors for this thread's two sorted slots (coalesced LDG.128,
    // L2-resident after the first block).
    const uint4* qt = (const uint4*)g_qtab.v;
    const uint4 d0 = qt[tid];
    const uint4 d1 = qt[tid + TPB];

    // Plane 0: PPB*64 floats = 128 float4 loads (threads 0..127)
    if (tid < PPB * (C_CH / 4)) {
        const float4* src = (const float4*)(x + (size_t)pix0 * C_CH);
        const int pix = pix0 + tid / (C_CH / 4);
        ((float4*)Bf)[tid] = (pix < npix) ? src[tid] : make_float4(0.f, 0.f, 0.f, 0.f);
    }
    __syncthreads();

    // Replica planes 1..3 (conflict-free scalar copies, 6 per thread)
    for (int t = tid; t < 3 * PLANE; t += TPB) {
        const int r = t % PLANE;
        const int c = r & 63;
        int sc = c + (1 + t / PLANE);
        if (sc > 63) sc = 63;
        Bf[PLANE + t] = Bf[(r - c) + sc];
    }
    __syncthreads();

    // Decode descriptors once into pointers.
    const char* bf  = (const char*)Bf;
    const bool  f0  = (d0.x >> 31) != 0;
    const bool  f1  = (d1.x >> 31) != 0;
    const bool  a1  = d1.y < NQ;               // slot0 always active
    const char* xi0 = bf + (d0.x & 0xFFu);
    const char* sv0 = bf + ((d0.x >> 8) & 0x3FFFu);
    const char* xi1 = bf + (d1.x & 0xFFu);
    const char* sv1 = bf + ((d1.x >> 8) & 0x3FFFu);
    float4* o0 = (float4*)out + (size_t)pix0 * NQ + d0.y;
    float4* o1 = (float4*)out + (size_t)pix0 * NQ + (a1 ? d1.y : 0u);

    const int rem = npix - pix0;
    const int pc  = rem >= PPB ? PPB : rem;

    // Outer pixel loop, unroll 1 (R2's proven geometry): per iteration the
    // whole block writes one pixel's contiguous 8 KB.
    #pragma unroll 1
    for (int p = 0; p < pc; ++p) {
        // ---- slot 0 ----
        if (f0) {
            const float  xi = *(const float*)xi0;
            const float4 v  = *(const float4*)sv0;
            float4 r;
            r.x = xi * v.x; r.y = xi * v.y; r.z = xi * v.z; r.w = xi * v.w;
            *o0 = r;
        } else {
            const unsigned z = d0.z, w = d0.w;
            float4 r;
            r.x = *(const float*)(bf + (z & 255u))         * *(const float*)(bf + ((z >> 8) & 255u));
            r.y = *(const float*)(bf + ((z >> 16) & 255u)) * *(const float*)(bf + (z >> 24));
            r.z = *(const float*)(bf + (w & 255u))         * *(const float*)(bf + ((w >> 8) & 255u));
            r.w = *(const float*)(bf + ((w >> 16) & 255u)) * *(const float*)(bf + (w >> 24));
            *o0 = r;
        }
        // ---- slot 1 ----
        if (f1) {
            const float  xi = *(const float*)xi1;
            const float4 v  = *(const float4*)sv1;
            float4 r;
            r.x = xi * v.x; r.y = xi * v.y; r.z = xi * v.z; r.w = xi * v.w;
            *o1 = r;
        } else if (a1) {
            const unsigned z = d1.z, w = d1.w;
            float4 r;
            r.x = *(const float*)(bf + (z & 255u))         * *(const float*)(bf + ((z >> 8) & 255u));
            r.y = *(const float*)(bf + ((z >> 16) & 255u)) * *(const float*)(bf + (z >> 24));
            r.z = *(const float*)(bf + (w & 255u))         * *(const float*)(bf + ((w >> 8) & 255u));
            r.w = *(const float*)(bf + ((w >> 16) & 255u)) * *(const float*)(bf + (w >> 24));
            *o1 = r;
        }
        // advance one pixel
        bf  += 256;  xi0 += 256;  sv0 += 256;  xi1 += 256;  sv1 += 256;
        o0  += NQ;   o1  += NQ;
    }
}

extern "C" void kernel_launch(void* const* d_in, const int* in_sizes, int n_in,
                              void* d_out, int out_size) {
    const float* x = (const float*)d_in[0];
    float* out = (float*)d_out;

    const int npix = in_sizes[0] / C_CH;            // 65536
    const int nblk = (npix + PPB - 1) / PPB;        // 8192

    channelpair_kernel<<<nblk, TPB>>>(x, out, npix);
}